// round 9
// baseline (speedup 1.0000x reference)
#include <cuda_runtime.h>
#include <cstdint>
#include <cstddef>

// ---------------------------------------------------------------------------
// QAOA diff quantum simulator, N=18 qubits, B=8, 4 layers.
// R9: ONE persistent kernel, PER-BATCH device barriers (32 blocks each) with
//     __nanosleep backoff -> the 8 independent batch chains skew and overlap,
//     hiding each pass's convoy latency under other batches' compute.
//     Kernel bodies = R7 (packed f32x2, 2 smem exchanges + shuffle bit,
//     fused hp + energy). Cross-block global reads use __ldcg (L2-only; L1
//     is not coherent across blocks within one launch).
// Layouts / residencies identical to R7:
//   element = amp pair (bit0); e-space 17 bits = cb(5) + local(12)=tid(8)+r(4)
//   S0: r=local8..11 ; S1: r=local4..7 ; S2: r=local0..3
//   LAY0: e=cb<<12|L ; LAY1: pre(L3,L8..11)=amp13..17 ; LAY2: pre=amp8..12
//   pass: LDG(S0,.cg) -> pre{r8..11 + shfl L3} -> phi -> main r8..11
//         -> X->S1 r4..7 -> X->S2 r0..3 + amp0 -> STG
// ---------------------------------------------------------------------------

namespace {
constexpr int NQ   = 18;
constexpr int QDIM = 1 << NQ;             // 262144 amps
constexpr int EDIM = QDIM / 2;            // 131072 elements
constexpr int NB   = 8;
constexpr int NL   = 4;
constexpr int TPB  = 256;
constexpr int EPT  = 16;                  // elements per thread (r = 4 bits)
constexpr int CHUNKE = TPB * EPT;         // 4096 elements (12 bits)
constexpr int CPB  = EDIM / CHUNKE;       // 32 chunks per batch
constexpr int BLOCKS = NB * CPB;          // 256 (all co-resident at 2/SM)
constexpr size_t SMEM_BYTES = (size_t)CHUNKE * 16; // 64 KB
}

__device__ __align__(256) float4 g_state[(size_t)NB * EDIM]; // 16 MB
__device__ __align__(16) unsigned char g_hp[(size_t)NB * QDIM]; // 2 MB
// per-batch barrier state, one 128B line per batch for each array
__device__ __align__(128) unsigned g_cnt[NB * 32];
__device__ __align__(128) unsigned g_gen[NB * 32];

// --------------------------- packed f32x2 helpers ---------------------------

using u64 = unsigned long long;

__device__ __forceinline__ u64 pk2(float lo, float hi) {
  u64 d; asm("mov.b64 %0, {%1, %2};" : "=l"(d) : "f"(lo), "f"(hi)); return d;
}
__device__ __forceinline__ void upk2(float& lo, float& hi, u64 v) {
  asm("mov.b64 {%0, %1}, %2;" : "=f"(lo), "=f"(hi) : "l"(v));
}
__device__ __forceinline__ u64 mul2(u64 a, u64 b) {
  u64 d; asm("mul.rn.f32x2 %0, %1, %2;" : "=l"(d) : "l"(a), "l"(b)); return d;
}
__device__ __forceinline__ u64 fma2(u64 a, u64 b, u64 c) {
  u64 d; asm("fma.rn.f32x2 %0, %1, %2, %3;" : "=l"(d) : "l"(a), "l"(b), "l"(c));
  return d;
}
__device__ __forceinline__ u64 swp2(u64 v) {
  float lo, hi; upk2(lo, hi, v); return pk2(hi, lo);
}

struct El { u64 re, im; };

__device__ __forceinline__ void rot2(El& x, El& y, u64 cc, u64 ss, u64 ns) {
  u64 t1 = mul2(ss, y.im);
  u64 t2 = mul2(ns, y.re);
  u64 t3 = mul2(ss, x.im);
  u64 t4 = mul2(ns, x.re);
  x.re = fma2(cc, x.re, t1);
  x.im = fma2(cc, x.im, t2);
  y.re = fma2(cc, y.re, t3);
  y.im = fma2(cc, y.im, t4);
}
__device__ __forceinline__ void rot2_lane(El& x, u64 cc, u64 ss, u64 ns) {
  u64 sre = swp2(x.re), sim = swp2(x.im);
  x.re = fma2(cc, x.re, mul2(ss, sim));
  x.im = fma2(cc, x.im, mul2(ns, sre));
}
__device__ __forceinline__ void rot2_shfl(El& x, int lanemask, u64 cc, u64 ss, u64 ns) {
  u64 pre = __shfl_xor_sync(0xffffffffu, x.re, lanemask);
  u64 pim = __shfl_xor_sync(0xffffffffu, x.im, lanemask);
  x.re = fma2(cc, x.re, mul2(ss, pim));
  x.im = fma2(cc, x.im, mul2(ns, pre));
}

template<int P>
__device__ __forceinline__ void btfE(El* a, u64 cc, u64 ss, u64 ns) {
#pragma unroll
  for (int h = 0; h < EPT / 2; h++) {
    int i0 = ((h >> P) << (P + 1)) | (h & ((1 << P) - 1));
    rot2(a[i0], a[i0 | (1 << P)], cc, ss, ns);
  }
}
__device__ __forceinline__ void btf4(El* a, u64 cc, u64 ss, u64 ns) {
  btfE<0>(a, cc, ss, ns); btfE<1>(a, cc, ss, ns);
  btfE<2>(a, cc, ss, ns); btfE<3>(a, cc, ss, ns);
}

// --------------------------- mappings ---------------------------------------

__device__ __forceinline__ int swz(int s) { return s ^ ((s >> 4) & 15); }

template<int LAY>
__device__ __forceinline__ int dmap(int cb, int L) {
  if (LAY == 0)        // P1: cb = e12..16
    return (cb << 12) | L;
  else if (LAY == 1)   // P2/P4: pre (L3, L8..11) = e12..16 = amp13..17
    return (L & 7) | (((L >> 4) & 15) << 3) | (cb << 7)
         | (((L >> 3) & 1) << 12) | ((L >> 8) << 13);
  else                 // P3/P5: pre (L3, L8..11) = e7..11 = amp8..12
    return (L & 7) | (((L >> 4) & 15) << 3) | (((L >> 3) & 1) << 7)
         | (((L >> 8) & 15) << 8) | (cb << 12);
}
__device__ __forceinline__ int locS0(int t, int r) { return (r << 8) | t; }
__device__ __forceinline__ int locS1(int t, int r) { return ((t >> 4) << 8) | (r << 4) | (t & 15); }
__device__ __forceinline__ int locS2(int t, int r) { return (t << 4) | r; }

// --------------------------- element I/O -------------------------------------

__device__ __forceinline__ El ld_el_cg(const float4* p, int e) {  // L2-only
  float4 v = __ldcg(p + e);
  El x; x.re = pk2(v.x, v.y); x.im = pk2(v.z, v.w); return x;
}
__device__ __forceinline__ void st_el(float4* p, int e, El x) {
  float4 v; upk2(v.x, v.y, x.re); upk2(v.z, v.w, x.im);
  p[e] = v;
}
__device__ __forceinline__ El lds_el(const float4* p, int s) {
  float4 v = p[s];
  El x; x.re = pk2(v.x, v.y); x.im = pk2(v.z, v.w); return x;
}

__device__ __forceinline__ void ph2(El& x, float2 p0, float2 p1) {
  u64 C  = pk2(p0.x, p1.x);
  u64 S  = pk2(p0.y, p1.y);
  u64 nS = pk2(-p0.y, -p1.y);
  u64 t = mul2(S, x.im);
  u64 u = mul2(nS, x.re);
  x.re = fma2(C, x.re, t);
  x.im = fma2(C, x.im, u);
}

// --------------------------- per-batch barrier --------------------------------

__device__ __forceinline__ void bbar(int b, int tid) {
  __syncthreads();
  if (tid == 0) {
    volatile unsigned* g = &g_gen[b * 32];
    unsigned gen = *g;
    __threadfence();
    if (atomicAdd(&g_cnt[b * 32], 1u) == CPB - 1) {
      g_cnt[b * 32] = 0;
      __threadfence();
      atomicAdd(&g_gen[b * 32], 1u);
    } else {
      while (*g == gen) __nanosleep(64);
      __threadfence();
    }
  }
  __syncthreads();
}

// --------------------------- down pass body ----------------------------------

template<int LAY>
__device__ __forceinline__ void down_body(
    float4* sh, const float2* ph_tab, const unsigned char* hpb, float4* st4,
    int cb, int tid, float cp, float sp, float cm, float sm) {
  const u64 ccp = pk2(cp, cp), ssp = pk2(sp, sp), nsp = pk2(-sp, -sp);
  const u64 ccm = pk2(cm, cm), ssm = pk2(sm, sm), nsm = pk2(-sm, -sm);

  El a[EPT];
  unsigned short hw[EPT];
#pragma unroll
  for (int r = 0; r < EPT; r++) {
    int e = dmap<LAY>(cb, locS0(tid, r));
    a[r] = ld_el_cg(st4, e);
    hw[r] = __ldcg(reinterpret_cast<const unsigned short*>(hpb + 2 * (size_t)e));
  }
  // pre: previous layer leftover = local {8..11} (regs) + local3 (lane bit 3)
  btf4(a, ccp, ssp, nsp);
#pragma unroll
  for (int r = 0; r < EPT; r++) rot2_shfl(a[r], 8, ccp, ssp, nsp);
  // phi
#pragma unroll
  for (int r = 0; r < EPT; r++)
    ph2(a[r], ph_tab[hw[r] & 0xFF], ph_tab[hw[r] >> 8]);
  // main: local 8..11
  btf4(a, ccm, ssm, nsm);
  // X -> S1
#pragma unroll
  for (int r = 0; r < EPT; r++) st_el(sh, swz(locS0(tid, r)), a[r]);
  __syncthreads();
#pragma unroll
  for (int r = 0; r < EPT; r++) a[r] = lds_el(sh, swz(locS1(tid, r)));
  btf4(a, ccm, ssm, nsm);                // local 4..7
  // X -> S2 (per-thread RMW store)
#pragma unroll
  for (int r = 0; r < EPT; r++) st_el(sh, swz(locS1(tid, r)), a[r]);
  __syncthreads();
#pragma unroll
  for (int r = 0; r < EPT; r++) a[r] = lds_el(sh, swz(locS2(tid, r)));
  btf4(a, ccm, ssm, nsm);                // local 0..3
#pragma unroll
  for (int r = 0; r < EPT; r++) rot2_lane(a[r], ccm, ssm, nsm); // amp0
#pragma unroll
  for (int r = 0; r < EPT; r++)
    st_el(st4, dmap<LAY>(cb, locS2(tid, r)), a[r]);
}

// --------------------------- the one kernel ----------------------------------

__global__ void __launch_bounds__(TPB, 2)
qaoa_all(const float* __restrict__ betas, const float* __restrict__ adj,
         float* __restrict__ out) {
  extern __shared__ float4 sh[];
  __shared__ float2 ph_tab[256];
  __shared__ int s_rm[NQ];
  __shared__ int s_sk[NQ];
  __shared__ float s_red[TPB / 32];

  const int tid = threadIdx.x;
  const int b  = blockIdx.x >> 5;
  const int cb = blockIdx.x & 31;

  // ---- one-time setup ----
  { float sv, cv; sincosf((float)tid, &sv, &cv); ph_tab[tid] = make_float2(cv, sv); }
  if (tid < NQ) {
    int m = 0;
    const float* row = adj + (size_t)b * NQ * NQ + tid * NQ;
    for (int v = tid + 1; v < NQ; v++)
      if (row[v] > 0.5f) m |= 1 << (17 - v);
    s_rm[tid] = m;
    s_sk[tid] = __popc(m);
  }
  if (cb == 0 && tid == 0) out[b] = 0.f;   // re-zeroed every launch/replay
  float cs[NL], sn[NL];
#pragma unroll
  for (int t = 0; t < NL; t++) sincosf(betas[b * NL + t], &sn[t], &cs[t]);
  __syncthreads();

  unsigned char* hpb = g_hp + (size_t)b * QDIM;
  float4* st4 = g_state + (size_t)b * EDIM;

  // ---- P1: hp + init + phi1 + RX1 (layout A, up) ----
  {
    const int dbase = (cb << 13) | (tid << 5);
    unsigned int w[8];
    int ne = 0;
#pragma unroll
    for (int u = 0; u < NQ; u++) ne += s_sk[u];
    int cr[32];
#pragma unroll
    for (int j = 0; j < 32; j++) cr[j] = 0;
#pragma unroll
    for (int u = 0; u < NQ; u++) {
      const int m = s_rm[u];
      const int kk = s_sk[u] - 2 * __popc(dbase & m);
      const int mlow = m & 31;
      if (u < 13) {
        const int sgn = (dbase >> (17 - u)) & 1;
#pragma unroll
        for (int j = 0; j < 32; j++) {
          int t2 = kk - 2 * __popc(j & mlow);
          cr[j] += sgn ? -t2 : t2;
        }
      } else {
        const int sb = 17 - u;
#pragma unroll
        for (int j = 0; j < 32; j++) {
          int t2 = kk - 2 * __popc(j & mlow);
          cr[j] += ((j >> sb) & 1) ? -t2 : t2;
        }
      }
    }
#pragma unroll
    for (int q = 0; q < 8; q++) {
      unsigned int p = 0;
#pragma unroll
      for (int e = 0; e < 4; e++)
        p |= (unsigned int)((ne - cr[q * 4 + e]) >> 1) << (e * 8);
      w[q] = p;
    }
    uint4* hdst = reinterpret_cast<uint4*>(hpb + dbase);
    hdst[0] = make_uint4(w[0], w[1], w[2], w[3]);
    hdst[1] = make_uint4(w[4], w[5], w[6], w[7]);

    const u64 cc = pk2(cs[0], cs[0]), ss = pk2(sn[0], sn[0]), ns = pk2(-sn[0], -sn[0]);
    El a[EPT];
    const float inv = 0.001953125f;  // 1/sqrt(2^18)
#pragma unroll
    for (int r = 0; r < EPT; r++) {
      int k0 = (w[r >> 1] >> ((r & 1) << 4)) & 0xFF;
      int k1 = (w[r >> 1] >> (((r & 1) << 4) + 8)) & 0xFF;
      float2 p0 = ph_tab[k0], p1 = ph_tab[k1];
      a[r].re = pk2(inv * p0.x, inv * p1.x);
      a[r].im = pk2(-inv * p0.y, -inv * p1.y);
    }
    btf4(a, cc, ss, ns);                         // local 0..3
#pragma unroll
    for (int r = 0; r < EPT; r++) rot2_lane(a[r], cc, ss, ns);  // amp0
#pragma unroll
    for (int r = 0; r < EPT; r++) st_el(sh, swz(locS2(tid, r)), a[r]);
    __syncthreads();
#pragma unroll
    for (int r = 0; r < EPT; r++) a[r] = lds_el(sh, swz(locS1(tid, r)));
    btf4(a, cc, ss, ns);                         // local 4..7
#pragma unroll
    for (int r = 0; r < EPT; r++) st_el(sh, swz(locS1(tid, r)), a[r]); // RMW
    __syncthreads();
#pragma unroll
    for (int r = 0; r < EPT; r++) a[r] = lds_el(sh, swz(locS0(tid, r)));
    btf4(a, cc, ss, ns);                         // local 8..11
#pragma unroll
    for (int r = 0; r < EPT; r++)
      st_el(st4, dmap<0>(cb, locS0(tid, r)), a[r]);
  }
  bbar(b, tid);

  // ---- P2 / P3 / P4 ----
  down_body<1>(sh, ph_tab, hpb, st4, cb, tid, cs[0], sn[0], cs[1], sn[1]);
  bbar(b, tid);
  down_body<2>(sh, ph_tab, hpb, st4, cb, tid, cs[1], sn[1], cs[2], sn[2]);
  bbar(b, tid);
  down_body<1>(sh, ph_tab, hpb, st4, cb, tid, cs[2], sn[2], cs[3], sn[3]);
  bbar(b, tid);

  // ---- P5: pre RX4 + energy ----
  {
    const u64 ccp = pk2(cs[3], cs[3]), ssp = pk2(sn[3], sn[3]), nsp = pk2(-sn[3], -sn[3]);
    El a[EPT];
    unsigned short hw[EPT];
#pragma unroll
    for (int r = 0; r < EPT; r++) {
      int e = dmap<2>(cb, locS0(tid, r));
      a[r] = ld_el_cg(st4, e);
      hw[r] = __ldcg(reinterpret_cast<const unsigned short*>(hpb + 2 * (size_t)e));
    }
    btf4(a, ccp, ssp, nsp);
#pragma unroll
    for (int r = 0; r < EPT; r++) rot2_shfl(a[r], 8, ccp, ssp, nsp);

    float e = 0.f;
#pragma unroll
    for (int r = 0; r < EPT; r++) {
      u64 p2 = fma2(a[r].im, a[r].im, mul2(a[r].re, a[r].re));
      float p0, p1; upk2(p0, p1, p2);
      e = fmaf(p0, (float)(hw[r] & 0xFF), e);
      e = fmaf(p1, (float)(hw[r] >> 8), e);
    }
#pragma unroll
    for (int o = 16; o; o >>= 1) e += __shfl_down_sync(0xffffffffu, e, o);
    if ((tid & 31) == 0) s_red[tid >> 5] = e;
    __syncthreads();
    if (tid == 0) {
      float t = 0.f;
#pragma unroll
      for (int i = 0; i < TPB / 32; i++) t += s_red[i];
      atomicAdd(out + b, t);
    }
  }
}

// --------------------------- launch ----------------------------------------

extern "C" void kernel_launch(void* const* d_in, const int* in_sizes, int n_in,
                              void* d_out, int out_size) {
  const float* betas = (const float*)d_in[0];
  const float* adj   = (const float*)d_in[1];
  if (n_in >= 2 && in_sizes[0] != NB * NL) {
    betas = (const float*)d_in[1];
    adj   = (const float*)d_in[0];
  }
  float* out = (float*)d_out;
  (void)out_size;

  cudaFuncSetAttribute(qaoa_all, cudaFuncAttributeMaxDynamicSharedMemorySize,
                       (int)SMEM_BYTES);
  qaoa_all<<<BLOCKS, TPB, SMEM_BYTES>>>(betas, adj, out);
}

// round 10
// speedup vs baseline: 1.1880x; 1.1880x over previous
#include <cuda_runtime.h>
#include <cstdint>
#include <cstddef>

// ---------------------------------------------------------------------------
// QAOA diff quantum simulator, N=18 qubits, B=8, 4 layers.
// R10: R7 topology (5 kernels, PDL) with LANE-MAJOR global access:
//   both LDG and STG have warp lanes on element bits 0..4 (512B-dense),
//   eliminating the 32-wavefront STG scatter every prior version had.
//   Bits L0..4 rotate via warp shuffles (MIO pipe); ONE smem exchange/pass.
//
// element = amp pair (amp bit0): float4 {re0,re1,im0,im1}; e-space 17 bits
//   = cb(5) + L(12);  L = per-block local element bits.
// Residencies (t = tid 8 bits, r = 4 bits):
//   X: L = (t&31) | r<<5 | (t>>5)<<9   regs=L5..8, lanes=L0..4, warp=L9..11
//   Y: L = t | r<<8                    regs=L8..11, lanes=L0..4, warp=L5..7
//   Z: L = r | (t&31)<<4 | (t>>5)<<9   regs=L0..3, lanes=L4..8 (P1 only)
// Layouts:
//   A: e = cb<<12 | L                       (leftover = cb = amp13..17)
//   B: L0..3->e0..3, cb->e4..8, L9..11->e9..11, L4->e12, L5..8->e13..16
//                                            (leftover = cb = amp5..9)
//   => pre (prev layer leftover) == L4..8 in BOTH layouts
//      = X regs (L5..8, btf4) + shfl mask16 (L4).
// Down pass: LDG(X) -> pre{btf4 + shfl16} -> phi -> main{btf4 L5..8,
//   shfl 16,8,4,2,1 = L4..0, lane-swap amp0} -> X->Y exchange (1 barrier)
//   -> btfE<1..3> = L9..11 -> STG(Y, dense).
// P1: hp in regs (Z-native) -> init+phi -> main{btf4 L0..3, shfl L4..8,
//   amp0} -> Z->Y -> L9..11 -> STG. P5: LDG(X) -> pre -> energy.
// ---------------------------------------------------------------------------

namespace {
constexpr int NQ   = 18;
constexpr int QDIM = 1 << NQ;             // 262144 amps
constexpr int EDIM = QDIM / 2;            // 131072 elements
constexpr int NB   = 8;
constexpr int NL   = 4;
constexpr int TPB  = 256;
constexpr int EPT  = 16;                  // elements per thread
constexpr int CHUNKE = TPB * EPT;         // 4096 elements (12 bits)
constexpr int CPB  = EDIM / CHUNKE;       // 32
constexpr int BLOCKS = NB * CPB;          // 256
constexpr size_t SMEM_BYTES = (size_t)CHUNKE * 16; // 64 KB
}

__device__ __align__(256) float4 g_state[(size_t)NB * EDIM]; // 16 MB
__device__ __align__(16) unsigned char g_hp[(size_t)NB * QDIM]; // 2 MB

// --------------------------- packed f32x2 helpers ---------------------------

using u64 = unsigned long long;

__device__ __forceinline__ u64 pk2(float lo, float hi) {
  u64 d; asm("mov.b64 %0, {%1, %2};" : "=l"(d) : "f"(lo), "f"(hi)); return d;
}
__device__ __forceinline__ void upk2(float& lo, float& hi, u64 v) {
  asm("mov.b64 {%0, %1}, %2;" : "=f"(lo), "=f"(hi) : "l"(v));
}
__device__ __forceinline__ u64 mul2(u64 a, u64 b) {
  u64 d; asm("mul.rn.f32x2 %0, %1, %2;" : "=l"(d) : "l"(a), "l"(b)); return d;
}
__device__ __forceinline__ u64 fma2(u64 a, u64 b, u64 c) {
  u64 d; asm("fma.rn.f32x2 %0, %1, %2, %3;" : "=l"(d) : "l"(a), "l"(b), "l"(c));
  return d;
}
__device__ __forceinline__ u64 swp2(u64 v) {
  float lo, hi; upk2(lo, hi, v); return pk2(hi, lo);
}

struct El { u64 re, im; };

__device__ __forceinline__ void rot2(El& x, El& y, u64 cc, u64 ss, u64 ns) {
  u64 t1 = mul2(ss, y.im);
  u64 t2 = mul2(ns, y.re);
  u64 t3 = mul2(ss, x.im);
  u64 t4 = mul2(ns, x.re);
  x.re = fma2(cc, x.re, t1);
  x.im = fma2(cc, x.im, t2);
  y.re = fma2(cc, y.re, t3);
  y.im = fma2(cc, y.im, t4);
}
__device__ __forceinline__ void rot2_lane(El& x, u64 cc, u64 ss, u64 ns) {
  u64 sre = swp2(x.re), sim = swp2(x.im);
  x.re = fma2(cc, x.re, mul2(ss, sim));
  x.im = fma2(cc, x.im, mul2(ns, sre));
}
__device__ __forceinline__ void rot2_shfl(El& x, int m, u64 cc, u64 ss, u64 ns) {
  u64 pre = __shfl_xor_sync(0xffffffffu, x.re, m);
  u64 pim = __shfl_xor_sync(0xffffffffu, x.im, m);
  x.re = fma2(cc, x.re, mul2(ss, pim));
  x.im = fma2(cc, x.im, mul2(ns, pre));
}

template<int P>
__device__ __forceinline__ void btfE(El* a, u64 cc, u64 ss, u64 ns) {
#pragma unroll
  for (int h = 0; h < EPT / 2; h++) {
    int i0 = ((h >> P) << (P + 1)) | (h & ((1 << P) - 1));
    rot2(a[i0], a[i0 | (1 << P)], cc, ss, ns);
  }
}
__device__ __forceinline__ void btf4(El* a, u64 cc, u64 ss, u64 ns) {
  btfE<0>(a, cc, ss, ns); btfE<1>(a, cc, ss, ns);
  btfE<2>(a, cc, ss, ns); btfE<3>(a, cc, ss, ns);
}
// all five within-warp lane bits
__device__ __forceinline__ void shfl5(El* a, u64 cc, u64 ss, u64 ns) {
#pragma unroll
  for (int m = 16; m >= 1; m >>= 1)
#pragma unroll
    for (int r = 0; r < EPT; r++) rot2_shfl(a[r], m, cc, ss, ns);
}

__device__ __forceinline__ void ph2(El& x, float2 p0, float2 p1) {
  u64 C  = pk2(p0.x, p1.x);
  u64 S  = pk2(p0.y, p1.y);
  u64 nS = pk2(-p0.y, -p1.y);
  u64 t = mul2(S, x.im);
  u64 u = mul2(nS, x.re);
  x.re = fma2(C, x.re, t);
  x.im = fma2(C, x.im, u);
}

// --------------------------- mappings ---------------------------------------

__device__ __forceinline__ int swz(int s) { return s ^ ((s >> 4) & 15); }

template<int LAY>
__device__ __forceinline__ int dmap(int cb, int L) {
  if (LAY == 0)   // A
    return (cb << 12) | L;
  else            // B
    return (L & 15) | (cb << 4) | (((L >> 9) & 7) << 9)
         | (((L >> 4) & 1) << 12) | (((L >> 5) & 15) << 13);
}
__device__ __forceinline__ int locX(int t, int r) { return (t & 31) | (r << 5) | ((t >> 5) << 9); }
__device__ __forceinline__ int locY(int t, int r) { return t | (r << 8); }
__device__ __forceinline__ int locZ(int t, int r) { return r | ((t & 31) << 4) | ((t >> 5) << 9); }

// --------------------------- element I/O -------------------------------------

__device__ __forceinline__ El ld_el(const float4* p, int e) {
  float4 v = p[e];
  El x; x.re = pk2(v.x, v.y); x.im = pk2(v.z, v.w); return x;
}
__device__ __forceinline__ void st_el(float4* p, int e, El x) {
  float4 v; upk2(v.x, v.y, x.re); upk2(v.z, v.w, x.im);
  p[e] = v;
}

__device__ __forceinline__ void pdl_wait() {
  asm volatile("griddepcontrol.wait;" ::: "memory");
}

// finishing stage shared by all state-writing passes: exchange to Y,
// rotate L9..11, dense STG.
template<int LAY, int LOCSRC>
__device__ __forceinline__ void finish_Y(
    float4* sh, float4* st4, El* a, int cb, int tid,
    u64 ccm, u64 ssm, u64 nsm) {
#pragma unroll
  for (int r = 0; r < EPT; r++) {
    int s = (LOCSRC == 0) ? locX(tid, r) : locZ(tid, r);
    st_el(sh, swz(s), a[r]);
  }
  __syncthreads();
#pragma unroll
  for (int r = 0; r < EPT; r++) a[r] = ld_el(sh, swz(locY(tid, r)));
  btfE<1>(a, ccm, ssm, nsm);   // L9
  btfE<2>(a, ccm, ssm, nsm);   // L10
  btfE<3>(a, ccm, ssm, nsm);   // L11
#pragma unroll
  for (int r = 0; r < EPT; r++)
    st_el(st4, dmap<LAY>(cb, locY(tid, r)), a[r]);   // lanes on e0..4: dense
}

// --------------------------- P1: hp + init + phi1 + RX1 ----------------------

__global__ void __launch_bounds__(TPB, 2)
pass_init(const float* __restrict__ betas, const float* __restrict__ adj,
          float* __restrict__ out) {
  extern __shared__ float4 sh[];
  __shared__ float2 ph_tab[256];
  __shared__ int s_rm[NQ];
  __shared__ int s_sk[NQ];

  const int tid = threadIdx.x;
  const int b = blockIdx.x >> 5, cb = blockIdx.x & 31;

  { float sv, cv; sincosf((float)tid, &sv, &cv); ph_tab[tid] = make_float2(cv, sv); }
  if (tid < NQ) {
    int m = 0;
    const float* row = adj + (size_t)b * NQ * NQ + tid * NQ;
    for (int v = tid + 1; v < NQ; v++)
      if (row[v] > 0.5f) m |= 1 << (17 - v);
    s_rm[tid] = m;
    s_sk[tid] = __popc(m);
  }
  if (cb == 0 && tid == 0) out[b] = 0.f;
  float cm, sm; sincosf(betas[b * NL + 0], &sm, &cm);
  const u64 cc = pk2(cm, cm), ss = pk2(sm, sm), ns = pk2(-sm, -sm);
  __syncthreads();

  unsigned char* hpb = g_hp + (size_t)b * QDIM;
  float4* st4 = g_state + (size_t)b * EDIM;

  // hp for this thread's 32 consecutive amps (Z residency: 16 consec elements)
  const int e0 = dmap<0>(cb, locZ(tid, 0));   // locZ(t,0..15) = e0..e0+15
  const int dbase = e0 * 2;
  unsigned int w[8];
  {
    int ne = 0;
#pragma unroll
    for (int u = 0; u < NQ; u++) ne += s_sk[u];
    int cr[32];
#pragma unroll
    for (int j = 0; j < 32; j++) cr[j] = 0;
#pragma unroll
    for (int u = 0; u < NQ; u++) {
      const int m = s_rm[u];
      const int kk = s_sk[u] - 2 * __popc(dbase & m);
      const int mlow = m & 31;
      if (u < 13) {
        const int sgn = (dbase >> (17 - u)) & 1;
#pragma unroll
        for (int j = 0; j < 32; j++) {
          int t2 = kk - 2 * __popc(j & mlow);
          cr[j] += sgn ? -t2 : t2;
        }
      } else {
        const int sb = 17 - u;
#pragma unroll
        for (int j = 0; j < 32; j++) {
          int t2 = kk - 2 * __popc(j & mlow);
          cr[j] += ((j >> sb) & 1) ? -t2 : t2;
        }
      }
    }
#pragma unroll
    for (int q = 0; q < 8; q++) {
      unsigned int p = 0;
#pragma unroll
      for (int e = 0; e < 4; e++)
        p |= (unsigned int)((ne - cr[q * 4 + e]) >> 1) << (e * 8);
      w[q] = p;
    }
    uint4* hdst = reinterpret_cast<uint4*>(hpb + dbase);
    hdst[0] = make_uint4(w[0], w[1], w[2], w[3]);
    hdst[1] = make_uint4(w[4], w[5], w[6], w[7]);
  }

  // init + phi1 in Z (r = L0..3, lanes = L4..8)
  El a[EPT];
  const float inv = 0.001953125f;  // 1/sqrt(2^18)
#pragma unroll
  for (int r = 0; r < EPT; r++) {
    int k0 = (w[r >> 1] >> ((r & 1) << 4)) & 0xFF;
    int k1 = (w[r >> 1] >> (((r & 1) << 4) + 8)) & 0xFF;
    float2 p0 = ph_tab[k0], p1 = ph_tab[k1];
    a[r].re = pk2(inv * p0.x, inv * p1.x);
    a[r].im = pk2(-inv * p0.y, -inv * p1.y);
  }
  btf4(a, cc, ss, ns);          // L0..3
  shfl5(a, cc, ss, ns);         // L4..8 (lane bits)
#pragma unroll
  for (int r = 0; r < EPT; r++) rot2_lane(a[r], cc, ss, ns);  // amp0
  finish_Y<0, 1>(sh, st4, a, cb, tid, cc, ss, ns);            // L9..11 + STG
}

// --------------------------- down pass ---------------------------------------

template<int LAY>
__global__ void __launch_bounds__(TPB, 2)
pass_down(const float* __restrict__ betas, int pl) {
  extern __shared__ float4 sh[];
  __shared__ float2 ph_tab[256];

  const int tid = threadIdx.x;
  const int b = blockIdx.x >> 5, cb = blockIdx.x & 31;

  { float sv, cv; sincosf((float)tid, &sv, &cv); ph_tab[tid] = make_float2(cv, sv); }
  float cp, sp, cm, sm;
  sincosf(betas[b * NL + pl], &sp, &cp);
  sincosf(betas[b * NL + pl + 1], &sm, &cm);
  const u64 ccp = pk2(cp, cp), ssp = pk2(sp, sp), nsp = pk2(-sp, -sp);
  const u64 ccm = pk2(cm, cm), ssm = pk2(sm, sm), nsm = pk2(-sm, -sm);

  pdl_wait();

  const unsigned char* hpb = g_hp + (size_t)b * QDIM;
  float4* st4 = g_state + (size_t)b * EDIM;

  El a[EPT];
  unsigned short hw[EPT];
#pragma unroll
  for (int r = 0; r < EPT; r++) {
    int e = dmap<LAY>(cb, locX(tid, r));     // lanes on e0..3 (+e12): dense
    a[r] = ld_el(st4, e);
    hw[r] = *reinterpret_cast<const unsigned short*>(hpb + 2 * (size_t)e);
  }
  __syncthreads();                           // ph_tab ready

  // pre = L4..8 (both layouts): regs L5..8 + shfl mask16 (L4)
  btf4(a, ccp, ssp, nsp);
#pragma unroll
  for (int r = 0; r < EPT; r++) rot2_shfl(a[r], 16, ccp, ssp, nsp);
  // phi
#pragma unroll
  for (int r = 0; r < EPT; r++)
    ph2(a[r], ph_tab[hw[r] & 0xFF], ph_tab[hw[r] >> 8]);
  // main at X: L5..8 (regs), L0..4 (shfl), amp0
  btf4(a, ccm, ssm, nsm);
  shfl5(a, ccm, ssm, nsm);
#pragma unroll
  for (int r = 0; r < EPT; r++) rot2_lane(a[r], ccm, ssm, nsm);
  finish_Y<LAY, 0>(sh, st4, a, cb, tid, ccm, ssm, nsm);   // L9..11 + dense STG
}

// --------------------------- P5: pre RX4 + energy -----------------------------

__global__ void __launch_bounds__(TPB, 2)
pass_energy(const float* __restrict__ betas, float* __restrict__ out) {
  __shared__ float red[TPB / 32];

  const int tid = threadIdx.x;
  const int b = blockIdx.x >> 5, cb = blockIdx.x & 31;

  float cp, sp; sincosf(betas[b * NL + 3], &sp, &cp);
  const u64 ccp = pk2(cp, cp), ssp = pk2(sp, sp), nsp = pk2(-sp, -sp);

  pdl_wait();

  const unsigned char* hpb = g_hp + (size_t)b * QDIM;
  const float4* st4 = g_state + (size_t)b * EDIM;

  El a[EPT];
  unsigned short hw[EPT];
#pragma unroll
  for (int r = 0; r < EPT; r++) {
    int e = dmap<0>(cb, locX(tid, r));
    a[r] = ld_el(st4, e);
    hw[r] = *reinterpret_cast<const unsigned short*>(hpb + 2 * (size_t)e);
  }
  // pre RX4 = L4..8
  btf4(a, ccp, ssp, nsp);
#pragma unroll
  for (int r = 0; r < EPT; r++) rot2_shfl(a[r], 16, ccp, ssp, nsp);

  float e = 0.f;
#pragma unroll
  for (int r = 0; r < EPT; r++) {
    u64 p2 = fma2(a[r].im, a[r].im, mul2(a[r].re, a[r].re));
    float p0, p1; upk2(p0, p1, p2);
    e = fmaf(p0, (float)(hw[r] & 0xFF), e);
    e = fmaf(p1, (float)(hw[r] >> 8), e);
  }
#pragma unroll
  for (int o = 16; o; o >>= 1) e += __shfl_down_sync(0xffffffffu, e, o);
  if ((tid & 31) == 0) red[tid >> 5] = e;
  __syncthreads();
  if (tid == 0) {
    float t = 0.f;
#pragma unroll
    for (int i = 0; i < TPB / 32; i++) t += red[i];
    atomicAdd(out + b, t);
  }
}

// --------------------------- launch ----------------------------------------

template<typename K, typename... Args>
static void launch_pdl(K kern, size_t smem, Args... args) {
  cudaLaunchConfig_t cfg = {};
  cfg.gridDim = dim3(BLOCKS, 1, 1);
  cfg.blockDim = dim3(TPB, 1, 1);
  cfg.dynamicSmemBytes = smem;
  cfg.stream = 0;
  cudaLaunchAttribute at[1];
  at[0].id = cudaLaunchAttributeProgrammaticStreamSerialization;
  at[0].val.programmaticStreamSerializationAllowed = 1;
  cfg.attrs = at;
  cfg.numAttrs = 1;
  cudaLaunchKernelEx(&cfg, kern, args...);
}

extern "C" void kernel_launch(void* const* d_in, const int* in_sizes, int n_in,
                              void* d_out, int out_size) {
  const float* betas = (const float*)d_in[0];
  const float* adj   = (const float*)d_in[1];
  if (n_in >= 2 && in_sizes[0] != NB * NL) {
    betas = (const float*)d_in[1];
    adj   = (const float*)d_in[0];
  }
  float* out = (float*)d_out;
  (void)out_size;

  cudaFuncSetAttribute(pass_init,    cudaFuncAttributeMaxDynamicSharedMemorySize, (int)SMEM_BYTES);
  cudaFuncSetAttribute(pass_down<0>, cudaFuncAttributeMaxDynamicSharedMemorySize, (int)SMEM_BYTES);
  cudaFuncSetAttribute(pass_down<1>, cudaFuncAttributeMaxDynamicSharedMemorySize, (int)SMEM_BYTES);

  pass_init<<<BLOCKS, TPB, SMEM_BYTES>>>(betas, adj, out);   // hp + phi1 + RX1
  launch_pdl(pass_down<1>, SMEM_BYTES, betas, 0);  // RX1 13..17, phi2, RX2
  launch_pdl(pass_down<0>, SMEM_BYTES, betas, 1);  // RX2 5..9,   phi3, RX3
  launch_pdl(pass_down<1>, SMEM_BYTES, betas, 2);  // RX3 13..17, phi4, RX4
  launch_pdl(pass_energy, 0, betas, out);          // RX4 5..9 + energy
}

// round 11
// speedup vs baseline: 1.2863x; 1.0827x over previous
#include <cuda_runtime.h>
#include <cstdint>
#include <cstddef>

// ---------------------------------------------------------------------------
// QAOA diff quantum simulator, N=18 qubits, B=8, 4 layers.
// R11: R10 (lane-major global access, 1 smem exchange + shuffles, PDL)
//      + bit-sliced hp computation in P1:
//   cross(dbase|j) splits into (a) u<13: sign fixed by dbase -> contribution
//   linear in j's 5 bits via precomputed weights W[b]; (b) u>=13: 5-mask
//   inner loop with compile-time sign/mask folding.  ~2300 -> ~1000 ALU
//   ops/thread in P1.
// Everything else identical to R10 (see layout comments there).
// ---------------------------------------------------------------------------

namespace {
constexpr int NQ   = 18;
constexpr int QDIM = 1 << NQ;             // 262144 amps
constexpr int EDIM = QDIM / 2;            // 131072 elements
constexpr int NB   = 8;
constexpr int NL   = 4;
constexpr int TPB  = 256;
constexpr int EPT  = 16;                  // elements per thread
constexpr int CHUNKE = TPB * EPT;         // 4096 elements (12 bits)
constexpr int CPB  = EDIM / CHUNKE;       // 32
constexpr int BLOCKS = NB * CPB;          // 256
constexpr size_t SMEM_BYTES = (size_t)CHUNKE * 16; // 64 KB
}

__device__ __align__(256) float4 g_state[(size_t)NB * EDIM]; // 16 MB
__device__ __align__(16) unsigned char g_hp[(size_t)NB * QDIM]; // 2 MB

// --------------------------- packed f32x2 helpers ---------------------------

using u64 = unsigned long long;

__device__ __forceinline__ u64 pk2(float lo, float hi) {
  u64 d; asm("mov.b64 %0, {%1, %2};" : "=l"(d) : "f"(lo), "f"(hi)); return d;
}
__device__ __forceinline__ void upk2(float& lo, float& hi, u64 v) {
  asm("mov.b64 {%0, %1}, %2;" : "=f"(lo), "=f"(hi) : "l"(v));
}
__device__ __forceinline__ u64 mul2(u64 a, u64 b) {
  u64 d; asm("mul.rn.f32x2 %0, %1, %2;" : "=l"(d) : "l"(a), "l"(b)); return d;
}
__device__ __forceinline__ u64 fma2(u64 a, u64 b, u64 c) {
  u64 d; asm("fma.rn.f32x2 %0, %1, %2, %3;" : "=l"(d) : "l"(a), "l"(b), "l"(c));
  return d;
}
__device__ __forceinline__ u64 swp2(u64 v) {
  float lo, hi; upk2(lo, hi, v); return pk2(hi, lo);
}

struct El { u64 re, im; };

__device__ __forceinline__ void rot2(El& x, El& y, u64 cc, u64 ss, u64 ns) {
  u64 t1 = mul2(ss, y.im);
  u64 t2 = mul2(ns, y.re);
  u64 t3 = mul2(ss, x.im);
  u64 t4 = mul2(ns, x.re);
  x.re = fma2(cc, x.re, t1);
  x.im = fma2(cc, x.im, t2);
  y.re = fma2(cc, y.re, t3);
  y.im = fma2(cc, y.im, t4);
}
__device__ __forceinline__ void rot2_lane(El& x, u64 cc, u64 ss, u64 ns) {
  u64 sre = swp2(x.re), sim = swp2(x.im);
  x.re = fma2(cc, x.re, mul2(ss, sim));
  x.im = fma2(cc, x.im, mul2(ns, sre));
}
__device__ __forceinline__ void rot2_shfl(El& x, int m, u64 cc, u64 ss, u64 ns) {
  u64 pre = __shfl_xor_sync(0xffffffffu, x.re, m);
  u64 pim = __shfl_xor_sync(0xffffffffu, x.im, m);
  x.re = fma2(cc, x.re, mul2(ss, pim));
  x.im = fma2(cc, x.im, mul2(ns, pre));
}

template<int P>
__device__ __forceinline__ void btfE(El* a, u64 cc, u64 ss, u64 ns) {
#pragma unroll
  for (int h = 0; h < EPT / 2; h++) {
    int i0 = ((h >> P) << (P + 1)) | (h & ((1 << P) - 1));
    rot2(a[i0], a[i0 | (1 << P)], cc, ss, ns);
  }
}
__device__ __forceinline__ void btf4(El* a, u64 cc, u64 ss, u64 ns) {
  btfE<0>(a, cc, ss, ns); btfE<1>(a, cc, ss, ns);
  btfE<2>(a, cc, ss, ns); btfE<3>(a, cc, ss, ns);
}
__device__ __forceinline__ void shfl5(El* a, u64 cc, u64 ss, u64 ns) {
#pragma unroll
  for (int m = 16; m >= 1; m >>= 1)
#pragma unroll
    for (int r = 0; r < EPT; r++) rot2_shfl(a[r], m, cc, ss, ns);
}

__device__ __forceinline__ void ph2(El& x, float2 p0, float2 p1) {
  u64 C  = pk2(p0.x, p1.x);
  u64 S  = pk2(p0.y, p1.y);
  u64 nS = pk2(-p0.y, -p1.y);
  u64 t = mul2(S, x.im);
  u64 u = mul2(nS, x.re);
  x.re = fma2(C, x.re, t);
  x.im = fma2(C, x.im, u);
}

// --------------------------- mappings ---------------------------------------

__device__ __forceinline__ int swz(int s) { return s ^ ((s >> 4) & 15); }

template<int LAY>
__device__ __forceinline__ int dmap(int cb, int L) {
  if (LAY == 0)   // A
    return (cb << 12) | L;
  else            // B
    return (L & 15) | (cb << 4) | (((L >> 9) & 7) << 9)
         | (((L >> 4) & 1) << 12) | (((L >> 5) & 15) << 13);
}
__device__ __forceinline__ int locX(int t, int r) { return (t & 31) | (r << 5) | ((t >> 5) << 9); }
__device__ __forceinline__ int locY(int t, int r) { return t | (r << 8); }
__device__ __forceinline__ int locZ(int t, int r) { return r | ((t & 31) << 4) | ((t >> 5) << 9); }

// --------------------------- element I/O -------------------------------------

__device__ __forceinline__ El ld_el(const float4* p, int e) {
  float4 v = p[e];
  El x; x.re = pk2(v.x, v.y); x.im = pk2(v.z, v.w); return x;
}
__device__ __forceinline__ void st_el(float4* p, int e, El x) {
  float4 v; upk2(v.x, v.y, x.re); upk2(v.z, v.w, x.im);
  p[e] = v;
}

__device__ __forceinline__ void pdl_wait() {
  asm volatile("griddepcontrol.wait;" ::: "memory");
}

template<int LAY, int LOCSRC>
__device__ __forceinline__ void finish_Y(
    float4* sh, float4* st4, El* a, int cb, int tid,
    u64 ccm, u64 ssm, u64 nsm) {
#pragma unroll
  for (int r = 0; r < EPT; r++) {
    int s = (LOCSRC == 0) ? locX(tid, r) : locZ(tid, r);
    st_el(sh, swz(s), a[r]);
  }
  __syncthreads();
#pragma unroll
  for (int r = 0; r < EPT; r++) a[r] = ld_el(sh, swz(locY(tid, r)));
  btfE<1>(a, ccm, ssm, nsm);   // L9
  btfE<2>(a, ccm, ssm, nsm);   // L10
  btfE<3>(a, ccm, ssm, nsm);   // L11
#pragma unroll
  for (int r = 0; r < EPT; r++)
    st_el(st4, dmap<LAY>(cb, locY(tid, r)), a[r]);
}

// --------------------------- P1: hp + init + phi1 + RX1 ----------------------

__global__ void __launch_bounds__(TPB, 2)
pass_init(const float* __restrict__ betas, const float* __restrict__ adj,
          float* __restrict__ out) {
  extern __shared__ float4 sh[];
  __shared__ float2 ph_tab[256];
  __shared__ int s_rm[NQ];
  __shared__ int s_sk[NQ];

  const int tid = threadIdx.x;
  const int b = blockIdx.x >> 5, cb = blockIdx.x & 31;

  { float sv, cv; sincosf((float)tid, &sv, &cv); ph_tab[tid] = make_float2(cv, sv); }
  if (tid < NQ) {
    int m = 0;
    const float* row = adj + (size_t)b * NQ * NQ + tid * NQ;
    for (int v = tid + 1; v < NQ; v++)
      if (row[v] > 0.5f) m |= 1 << (17 - v);
    s_rm[tid] = m;
    s_sk[tid] = __popc(m);
  }
  if (cb == 0 && tid == 0) out[b] = 0.f;
  float cm, sm; sincosf(betas[b * NL + 0], &sm, &cm);
  const u64 cc = pk2(cm, cm), ss = pk2(sm, sm), ns = pk2(-sm, -sm);
  __syncthreads();

  unsigned char* hpb = g_hp + (size_t)b * QDIM;
  float4* st4 = g_state + (size_t)b * EDIM;

  // ---- hp via bit-slicing (thread covers amps dbase..dbase+31) ----
  const int e0 = dmap<0>(cb, locZ(tid, 0));
  const int dbase = e0 * 2;
  unsigned int w[8];
  {
    int ne = 0;
#pragma unroll
    for (int u = 0; u < NQ; u++) ne += s_sk[u];

    // u < 13: sign fixed by dbase -> fold to C0 + linear bit-weights W2[b]=2*W[b]
    int C0 = 0;
    int W2[5] = {0, 0, 0, 0, 0};
#pragma unroll
    for (int u = 0; u < 13; u++) {
      const int m = s_rm[u];
      const int kk = s_sk[u] - 2 * __popc(dbase & m);
      const bool neg = (dbase >> (17 - u)) & 1;
      C0 += neg ? -kk : kk;
      const int d2 = neg ? -2 : 2;
#pragma unroll
      for (int bpos = 0; bpos < 5; bpos++)
        if ((m >> bpos) & 1) W2[bpos] += d2;
    }
    // u >= 13: sign bit lives in j (bit 17-u); keep 5-mask inner loop
    int kk5[5], ml5[5];
#pragma unroll
    for (int k = 0; k < 5; k++) {
      const int u = 13 + k;
      kk5[k] = s_sk[u] - 2 * __popc(dbase & s_rm[u]);
      ml5[k] = s_rm[u] & 31;
    }

    int cr[32];
#pragma unroll
    for (int j = 0; j < 32; j++) {
      int acc = C0;
#pragma unroll
      for (int bpos = 0; bpos < 5; bpos++)
        if (j & (1 << bpos)) acc -= W2[bpos];        // j const: folds away
#pragma unroll
      for (int k = 0; k < 5; k++) {
        int t2 = kk5[k] - 2 * __popc(j & ml5[k]);    // j const: AND-imm
        acc += ((j >> (4 - k)) & 1) ? -t2 : t2;      // j const: sign folds
      }
      cr[j] = acc;
    }
#pragma unroll
    for (int q = 0; q < 8; q++) {
      unsigned int p = 0;
#pragma unroll
      for (int e = 0; e < 4; e++)
        p |= (unsigned int)((ne - cr[q * 4 + e]) >> 1) << (e * 8);
      w[q] = p;
    }
    uint4* hdst = reinterpret_cast<uint4*>(hpb + dbase);
    hdst[0] = make_uint4(w[0], w[1], w[2], w[3]);
    hdst[1] = make_uint4(w[4], w[5], w[6], w[7]);
  }

  // ---- init + phi1 in Z (r = L0..3, lanes = L4..8) ----
  El a[EPT];
  const float inv = 0.001953125f;  // 1/sqrt(2^18)
#pragma unroll
  for (int r = 0; r < EPT; r++) {
    int k0 = (w[r >> 1] >> ((r & 1) << 4)) & 0xFF;
    int k1 = (w[r >> 1] >> (((r & 1) << 4) + 8)) & 0xFF;
    float2 p0 = ph_tab[k0], p1 = ph_tab[k1];
    a[r].re = pk2(inv * p0.x, inv * p1.x);
    a[r].im = pk2(-inv * p0.y, -inv * p1.y);
  }
  btf4(a, cc, ss, ns);          // L0..3
  shfl5(a, cc, ss, ns);         // L4..8 (lane bits)
#pragma unroll
  for (int r = 0; r < EPT; r++) rot2_lane(a[r], cc, ss, ns);  // amp0
  finish_Y<0, 1>(sh, st4, a, cb, tid, cc, ss, ns);            // L9..11 + STG
}

// --------------------------- down pass ---------------------------------------

template<int LAY>
__global__ void __launch_bounds__(TPB, 2)
pass_down(const float* __restrict__ betas, int pl) {
  extern __shared__ float4 sh[];
  __shared__ float2 ph_tab[256];

  const int tid = threadIdx.x;
  const int b = blockIdx.x >> 5, cb = blockIdx.x & 31;

  { float sv, cv; sincosf((float)tid, &sv, &cv); ph_tab[tid] = make_float2(cv, sv); }
  float cp, sp, cm, sm;
  sincosf(betas[b * NL + pl], &sp, &cp);
  sincosf(betas[b * NL + pl + 1], &sm, &cm);
  const u64 ccp = pk2(cp, cp), ssp = pk2(sp, sp), nsp = pk2(-sp, -sp);
  const u64 ccm = pk2(cm, cm), ssm = pk2(sm, sm), nsm = pk2(-sm, -sm);

  pdl_wait();

  const unsigned char* hpb = g_hp + (size_t)b * QDIM;
  float4* st4 = g_state + (size_t)b * EDIM;

  El a[EPT];
  unsigned short hw[EPT];
#pragma unroll
  for (int r = 0; r < EPT; r++) {
    int e = dmap<LAY>(cb, locX(tid, r));
    a[r] = ld_el(st4, e);
    hw[r] = *reinterpret_cast<const unsigned short*>(hpb + 2 * (size_t)e);
  }
  __syncthreads();                           // ph_tab ready

  // pre = L4..8: regs L5..8 + shfl mask16 (L4)
  btf4(a, ccp, ssp, nsp);
#pragma unroll
  for (int r = 0; r < EPT; r++) rot2_shfl(a[r], 16, ccp, ssp, nsp);
  // phi
#pragma unroll
  for (int r = 0; r < EPT; r++)
    ph2(a[r], ph_tab[hw[r] & 0xFF], ph_tab[hw[r] >> 8]);
  // main at X: L5..8 (regs), L0..4 (shfl), amp0
  btf4(a, ccm, ssm, nsm);
  shfl5(a, ccm, ssm, nsm);
#pragma unroll
  for (int r = 0; r < EPT; r++) rot2_lane(a[r], ccm, ssm, nsm);
  finish_Y<LAY, 0>(sh, st4, a, cb, tid, ccm, ssm, nsm);   // L9..11 + dense STG
}

// --------------------------- P5: pre RX4 + energy -----------------------------

__global__ void __launch_bounds__(TPB, 2)
pass_energy(const float* __restrict__ betas, float* __restrict__ out) {
  __shared__ float red[TPB / 32];

  const int tid = threadIdx.x;
  const int b = blockIdx.x >> 5, cb = blockIdx.x & 31;

  float cp, sp; sincosf(betas[b * NL + 3], &sp, &cp);
  const u64 ccp = pk2(cp, cp), ssp = pk2(sp, sp), nsp = pk2(-sp, -sp);

  pdl_wait();

  const unsigned char* hpb = g_hp + (size_t)b * QDIM;
  const float4* st4 = g_state + (size_t)b * EDIM;

  El a[EPT];
  unsigned short hw[EPT];
#pragma unroll
  for (int r = 0; r < EPT; r++) {
    int e = dmap<0>(cb, locX(tid, r));
    a[r] = ld_el(st4, e);
    hw[r] = *reinterpret_cast<const unsigned short*>(hpb + 2 * (size_t)e);
  }
  btf4(a, ccp, ssp, nsp);
#pragma unroll
  for (int r = 0; r < EPT; r++) rot2_shfl(a[r], 16, ccp, ssp, nsp);

  float e = 0.f;
#pragma unroll
  for (int r = 0; r < EPT; r++) {
    u64 p2 = fma2(a[r].im, a[r].im, mul2(a[r].re, a[r].re));
    float p0, p1; upk2(p0, p1, p2);
    e = fmaf(p0, (float)(hw[r] & 0xFF), e);
    e = fmaf(p1, (float)(hw[r] >> 8), e);
  }
#pragma unroll
  for (int o = 16; o; o >>= 1) e += __shfl_down_sync(0xffffffffu, e, o);
  if ((tid & 31) == 0) red[tid >> 5] = e;
  __syncthreads();
  if (tid == 0) {
    float t = 0.f;
#pragma unroll
    for (int i = 0; i < TPB / 32; i++) t += red[i];
    atomicAdd(out + b, t);
  }
}

// --------------------------- launch ----------------------------------------

template<typename K, typename... Args>
static void launch_pdl(K kern, size_t smem, Args... args) {
  cudaLaunchConfig_t cfg = {};
  cfg.gridDim = dim3(BLOCKS, 1, 1);
  cfg.blockDim = dim3(TPB, 1, 1);
  cfg.dynamicSmemBytes = smem;
  cfg.stream = 0;
  cudaLaunchAttribute at[1];
  at[0].id = cudaLaunchAttributeProgrammaticStreamSerialization;
  at[0].val.programmaticStreamSerializationAllowed = 1;
  cfg.attrs = at;
  cfg.numAttrs = 1;
  cudaLaunchKernelEx(&cfg, kern, args...);
}

extern "C" void kernel_launch(void* const* d_in, const int* in_sizes, int n_in,
                              void* d_out, int out_size) {
  const float* betas = (const float*)d_in[0];
  const float* adj   = (const float*)d_in[1];
  if (n_in >= 2 && in_sizes[0] != NB * NL) {
    betas = (const float*)d_in[1];
    adj   = (const float*)d_in[0];
  }
  float* out = (float*)d_out;
  (void)out_size;

  cudaFuncSetAttribute(pass_init,    cudaFuncAttributeMaxDynamicSharedMemorySize, (int)SMEM_BYTES);
  cudaFuncSetAttribute(pass_down<0>, cudaFuncAttributeMaxDynamicSharedMemorySize, (int)SMEM_BYTES);
  cudaFuncSetAttribute(pass_down<1>, cudaFuncAttributeMaxDynamicSharedMemorySize, (int)SMEM_BYTES);

  pass_init<<<BLOCKS, TPB, SMEM_BYTES>>>(betas, adj, out);   // hp + phi1 + RX1
  launch_pdl(pass_down<1>, SMEM_BYTES, betas, 0);  // RX1 13..17, phi2, RX2
  launch_pdl(pass_down<0>, SMEM_BYTES, betas, 1);  // RX2 5..9,   phi3, RX3
  launch_pdl(pass_down<1>, SMEM_BYTES, betas, 2);  // RX3 13..17, phi4, RX4
  launch_pdl(pass_energy, 0, betas, out);          // RX4 5..9 + energy
}